// round 8
// baseline (speedup 1.0000x reference)
#include <cuda_runtime.h>
#include <cuda_bf16.h>

// out[n, d] = dist[n] * w[d]   (N = 1,000,000 rows, DIM = 256, fp32)
// R7: contiguous-segment persistent kernel, 32-bit indexing.
//  - Each CTA owns one contiguous segment (base 256-aligned), inner stride
//    TPB=256 vec4 = 4096 B -> unrolled stores/loads use immediate offsets,
//    one pointer update per 8 stores.
//  - Thread column is fixed -> weight float4 in registers.
//  - __stcs evict-first streaming stores; __launch_bounds__(256,8) pins
//    occupancy at 8 CTAs/SM.

#define DIM 256
#define VEC4_PER_ROW (DIM / 4)   // 64
#define TPB 256
#define NBLK 1184                // 148 SMs * 8 resident CTAs -> 1 wave
#define UNROLL 8

__global__ __launch_bounds__(TPB, 8) void outer_product_seg(
    const float* __restrict__ dist,
    const float* __restrict__ weight,
    float4* __restrict__ out,
    unsigned total_vec4)         // n_rows * 64 = 64M < 2^32
{
    const int col4 = threadIdx.x & (VEC4_PER_ROW - 1);
    const float4 w = __ldg(&reinterpret_cast<const float4*>(weight)[col4]);

    // Contiguous segment per CTA, rounded to a multiple of TPB so every
    // segment base is 256-aligned (thread column stays fixed).
    unsigned per_seg = (total_vec4 + NBLK - 1) / NBLK;
    per_seg = ((per_seg + TPB - 1) / TPB) * TPB;            // 54272 for N=1e6
    const unsigned beg = blockIdx.x * per_seg;
    const unsigned end = min(beg + per_seg, total_vec4);

    unsigned i = beg + threadIdx.x;

    // Main loop: 8 x (4096 B apart) STG.128 per thread per iteration.
    // (i + j*TPB) >> 6 == (i >> 6) + 4*j exactly (i == tid mod 256), so the
    // dist loads are immediate-offset too, and warp-uniform broadcasts.
    for (; i + (UNROLL - 1) * TPB < end; i += UNROLL * TPB) {
        const unsigned row0 = i >> 6;
        float d[UNROLL];
#pragma unroll
        for (int j = 0; j < UNROLL; j++) {
            d[j] = __ldg(&dist[row0 + 4u * j]);
        }
#pragma unroll
        for (int j = 0; j < UNROLL; j++) {
            float4 r;
            r.x = d[j] * w.x;
            r.y = d[j] * w.y;
            r.z = d[j] * w.z;
            r.w = d[j] * w.w;
            __stcs(&out[i + j * TPB], r);
        }
    }

    // Tail.
    for (; i < end; i += TPB) {
        const float dd = __ldg(&dist[i >> 6]);
        float4 r;
        r.x = dd * w.x; r.y = dd * w.y; r.z = dd * w.z; r.w = dd * w.w;
        __stcs(&out[i], r);
    }
}

extern "C" void kernel_launch(void* const* d_in, const int* in_sizes, int n_in,
                              void* d_out, int out_size)
{
    const float* dist   = (const float*)d_in[0];
    const float* weight = (const float*)d_in[1];
    float4* out         = (float4*)d_out;

    unsigned total_vec4 = (unsigned)in_sizes[0] * VEC4_PER_ROW;  // 64M

    outer_product_seg<<<NBLK, TPB>>>(dist, weight, out, total_vec4);
}

// round 9
// speedup vs baseline: 1.0182x; 1.0182x over previous
#include <cuda_runtime.h>
#include <cuda_bf16.h>

// out[n, d] = dist[n] * w[d]   (N = 1,000,000 rows, DIM = 256, fp32)
// R8: best-of-both. R5's grid-stride interleave (empirically feeds the L2
// hash / DRAM channels best) + streaming stores, with R7's register economy:
// 32-bit indices and __launch_bounds__(256,8) to hold 8 CTAs/SM.

#define DIM 256
#define VEC4_PER_ROW (DIM / 4)   // 64
#define TPB 256
#define NBLK 1184                // 148 SMs * 8 resident CTAs -> 1 wave
#define UNROLL 8

__global__ __launch_bounds__(TPB, 8) void outer_product_gs(
    const float* __restrict__ dist,
    const float* __restrict__ weight,
    float4* __restrict__ out,
    unsigned total_vec4)         // n_rows * 64 = 64M < 2^32
{
    // Fixed column for this thread (grid stride is a multiple of 64).
    const int col4 = threadIdx.x & (VEC4_PER_ROW - 1);
    const float4 w = __ldg(&reinterpret_cast<const float4*>(weight)[col4]);

    const unsigned stride = NBLK * TPB;                  // 303104, mult of 64
    unsigned i = blockIdx.x * TPB + threadIdx.x;

    // Main loop: 8 interleaved rows per iteration. Dist loads front-batched
    // (warp-uniform broadcasts, L1/L2-resident); stores are evict-first
    // streaming STG.128 to keep the L2->DRAM writeback dense.
    for (; i + (UNROLL - 1) * stride < total_vec4; i += UNROLL * stride) {
        float d[UNROLL];
#pragma unroll
        for (int j = 0; j < UNROLL; j++) {
            d[j] = __ldg(&dist[(i + j * stride) >> 6]);
        }
#pragma unroll
        for (int j = 0; j < UNROLL; j++) {
            float4 r;
            r.x = d[j] * w.x;
            r.y = d[j] * w.y;
            r.z = d[j] * w.z;
            r.w = d[j] * w.w;
            __stcs(&out[i + j * stride], r);
        }
    }

    // Tail.
    for (; i < total_vec4; i += stride) {
        const float dd = __ldg(&dist[i >> 6]);
        float4 r;
        r.x = dd * w.x; r.y = dd * w.y; r.z = dd * w.z; r.w = dd * w.w;
        __stcs(&out[i], r);
    }
}

extern "C" void kernel_launch(void* const* d_in, const int* in_sizes, int n_in,
                              void* d_out, int out_size)
{
    const float* dist   = (const float*)d_in[0];
    const float* weight = (const float*)d_in[1];
    float4* out         = (float4*)d_out;

    unsigned total_vec4 = (unsigned)in_sizes[0] * VEC4_PER_ROW;  // 64M

    outer_product_gs<<<NBLK, TPB>>>(dist, weight, out, total_vec4);
}